// round 7
// baseline (speedup 1.0000x reference)
#include <cuda_runtime.h>
#include <cuda_bf16.h>
#include <math.h>
#include <stdint.h>

// Problem constants
#define B_SZ   8
#define L_SEQ  4096
#define D_MODEL 512
#define NC     128
#define NSTATE 64
#define NTAPS  32
#define M_ROWS (B_SZ * L_SEQ)   // 32768

// Scratch
__device__ float  g_z1 [M_ROWS * D_MODEL];
__device__ float  g_y  [M_ROWS * D_MODEL];
__device__ float  g_k  [NC * NTAPS];
__device__ float  g_wti[D_MODEL * D_MODEL];  // Win^T, tf32-rounded
__device__ float  g_wto[D_MODEL * D_MODEL];  // Wout^T, tf32-rounded
__device__ float2 g_stats[M_ROWS];           // (mu, rstd) per row

// ---------------------------------------------------------------------------
// Helpers
// ---------------------------------------------------------------------------
__device__ __forceinline__ float to_tf32(float f) {
    uint32_t u;
    asm("cvt.rna.tf32.f32 %0, %1;" : "=r"(u) : "f"(f));
    return __uint_as_float(u);
}
__device__ __forceinline__ uint32_t smem_u32(const void* p) {
    uint32_t a;
    asm("{ .reg .u64 t; cvta.to.shared.u64 t, %1; cvt.u32.u64 %0, t; }" : "=r"(a) : "l"(p));
    return a;
}
__device__ __forceinline__ void cp16(uint32_t dst, const void* src) {
    asm volatile("cp.async.cg.shared.global [%0], [%1], 16;" :: "r"(dst), "l"(src));
}
#define CP_COMMIT() asm volatile("cp.async.commit_group;" ::: "memory")
#define CP_WAIT(n)  asm volatile("cp.async.wait_group %0;" :: "n"(n) : "memory")

// m16n8k8 tf32 warp MMA
__device__ __forceinline__ void mma_tf32(float c[4],
                                         float a0, float a1, float a2, float a3,
                                         float b0, float b1)
{
    asm volatile(
        "mma.sync.aligned.m16n8k8.row.col.f32.tf32.tf32.f32 "
        "{%0,%1,%2,%3}, {%4,%5,%6,%7}, {%8,%9}, {%0,%1,%2,%3};"
        : "+f"(c[0]), "+f"(c[1]), "+f"(c[2]), "+f"(c[3])
        : "r"(__float_as_uint(a0)), "r"(__float_as_uint(a1)),
          "r"(__float_as_uint(a2)), "r"(__float_as_uint(a3)),
          "r"(__float_as_uint(b0)), "r"(__float_as_uint(b1)));
}

// f32x2 packed math
__device__ __forceinline__ uint64_t pk2(float a, float b) {
    uint64_t r; asm("mov.b64 %0, {%1, %2};" : "=l"(r) : "f"(a), "f"(b)); return r;
}
__device__ __forceinline__ void upk2(uint64_t v, float& a, float& b) {
    asm("mov.b64 {%0, %1}, %2;" : "=f"(a), "=f"(b) : "l"(v));
}
__device__ __forceinline__ uint64_t addx2(uint64_t a, uint64_t b) {
    uint64_t r; asm("add.rn.f32x2 %0, %1, %2;" : "=l"(r) : "l"(a), "l"(b)); return r;
}
__device__ __forceinline__ uint64_t mulx2(uint64_t a, uint64_t b) {
    uint64_t r; asm("mul.rn.f32x2 %0, %1, %2;" : "=l"(r) : "l"(a), "l"(b)); return r;
}
__device__ __forceinline__ uint64_t fmax2(uint64_t a, uint64_t b, uint64_t c) {
    uint64_t r; asm("fma.rn.f32x2 %0, %1, %2, %3;" : "=l"(r) : "l"(a), "l"(b), "l"(c)); return r;
}

// ---------------------------------------------------------------------------
// Combined prep kernel: [0,16384) LN stats | [16384,16640) Win^T |
// [16640,16896) Wout^T | [16896,16912) FIR taps.  256 threads.
// ---------------------------------------------------------------------------
#define PREP_STATS 16384
#define PREP_WIN   (PREP_STATS + 256)
#define PREP_WOUT  (PREP_WIN + 256)
#define PREP_KGEN  (PREP_WOUT + 16)

__global__ __launch_bounds__(256)
void prep_kernel(const float* __restrict__ x,
                 const float* __restrict__ Win, const float* __restrict__ Wout,
                 const float* __restrict__ lre, const float* __restrict__ lim,
                 const float* __restrict__ Bm,  const float* __restrict__ cre,
                 const float* __restrict__ cim)
{
    int bid = blockIdx.x;
    int tid = threadIdx.x;

    if (bid < PREP_STATS) {
        // LN stats: 2 rows per block, 128 threads each
        int half = tid >> 7;          // 0/1
        int t    = tid & 127;
        int row  = bid * 2 + half;
        float4 v = ((const float4*)(x + (size_t)row * D_MODEL))[t];
        float s  = v.x + v.y + v.z + v.w;
        float sq = v.x*v.x + v.y*v.y + v.z*v.z + v.w*v.w;
        #pragma unroll
        for (int off = 16; off > 0; off >>= 1) {
            s  += __shfl_xor_sync(0xFFFFFFFFu, s,  off);
            sq += __shfl_xor_sync(0xFFFFFFFFu, sq, off);
        }
        __shared__ float ss[8], ssq[8];
        int warp = tid >> 5, lane = tid & 31;
        if (lane == 0) { ss[warp] = s; ssq[warp] = sq; }
        __syncthreads();
        int w0 = half * 4;
        float tots = ss[w0] + ss[w0+1] + ss[w0+2] + ss[w0+3];
        float totq = ssq[w0] + ssq[w0+1] + ssq[w0+2] + ssq[w0+3];
        if (t == 0) {
            float mu  = tots * (1.0f / D_MODEL);
            float var = totq * (1.0f / D_MODEL) - mu * mu;
            g_stats[row] = make_float2(mu, rsqrtf(var + 1e-5f));
        }
    } else if (bid < PREP_WOUT) {
        // transpose + tf32 round, 32x32 tile
        int ti = bid - PREP_STATS;
        const float* W;
        float* Wt;
        if (ti < 256) { W = Win;  Wt = g_wti; }
        else          { W = Wout; Wt = g_wto; ti -= 256; }
        int n0 = (ti & 15) * 32, k0 = (ti >> 4) * 32;
        __shared__ float tile[32][33];
        int tx = tid & 31, ty = tid >> 5;   // 32 x 8
        #pragma unroll
        for (int j = 0; j < 32; j += 8)
            tile[ty + j][tx] = W[(size_t)(k0 + ty + j) * D_MODEL + n0 + tx];
        __syncthreads();
        #pragma unroll
        for (int j = 0; j < 32; j += 8)
            Wt[(size_t)(n0 + ty + j) * D_MODEL + k0 + tx] = to_tf32(tile[tx][ty + j]);
    } else {
        // FIR taps: 8 chunks per block
        int c = (bid - PREP_WOUT) * 8 + (tid >> 5);
        int tau = tid & 31;
        float ft = (float)tau;
        float acc = 0.0f;
        #pragma unroll 8
        for (int n = 0; n < NSTATE; n++) {
            int idx = c * NSTATE + n;
            float re = lre[idx], im = lim[idx], bn = Bm[idx];
            float cr = cre[idx] * bn, ci = cim[idx] * bn;
            float s, co;
            sincosf(im * ft, &s, &co);
            acc += expf(re * ft) * (cr * co - ci * s);
        }
        g_k[c * NTAPS + tau] = acc;
    }
}

// ---------------------------------------------------------------------------
// Warp-MMA tf32 GEMM. CTA tile 128x128, BK=32, 8 warps (2m x 4n), m16n8k8.
// LNA=1: A-producer reads x, applies LayerNorm (g_stats + smem gamma/beta),
//        tf32-rounds, STS (no cp.async for A).
// LNA=0: cp.async A.   EPI=1: gelu + residual epilogue.
// ---------------------------------------------------------------------------
__device__ __forceinline__ float gelu_exact(float v) {
    return 0.5f * v * (1.0f + erff(v * 0.70710678118654752f));
}

#define TILE_BYTES 16384                // 128 rows x 128B
#define GEMM_SMEM  (4 * TILE_BYTES)     // A0,B0,A1,B1

__device__ __forceinline__ void stage_cp(const float* __restrict__ src, uint32_t sbuf,
                                         int row0, int k0, int tid)
{
    #pragma unroll
    for (int i = 0; i < 4; i++) {
        int idx = tid + i * 256;
        int row = idx >> 3, c4 = idx & 7;
        const float* g = src + (((size_t)(row0 + row)) << 9) + k0 + (c4 << 2);
        uint32_t dst = sbuf + row * 128 + ((c4 ^ (row & 7)) << 4);
        cp16(dst, g);
    }
}

template<int EPI, int LNA>
__global__ __launch_bounds__(256)
void gemm_mma(const float* __restrict__ A, const float* __restrict__ Bt,
              const float* __restrict__ bias, const float* __restrict__ resid,
              float* __restrict__ C,
              const float* __restrict__ gam, const float* __restrict__ bet)
{
    extern __shared__ __align__(16) char sm[];
    char* sA[2] = { sm,                  sm + 2 * TILE_BYTES };
    const char* sB[2] = { sm + TILE_BYTES,     sm + 3 * TILE_BYTES };
    uint32_t uA[2] = { smem_u32(sm),                  smem_u32(sm + 2 * TILE_BYTES) };
    uint32_t uB[2] = { smem_u32(sm + TILE_BYTES),     smem_u32(sm + 3 * TILE_BYTES) };

    __shared__ float s_g[D_MODEL], s_b[D_MODEL];

    int tid = threadIdx.x;
    int lane = tid & 31;
    int wid  = tid >> 5;
    int wm = wid >> 2;       // 0..1
    int wn = wid & 3;        // 0..3
    int g  = lane >> 2;      // 0..7
    int t4 = lane & 3;       // 0..3

    int bn = blockIdx.x, bm = blockIdx.y;
    int rowA = bm * 128, rowB = bn * 128;

    // LNA: hoist per-thread stats + row pointers (stage-invariant)
    float2 st[4];
    const float* xrow[4];
    if (LNA) {
        if (tid < 128) {
            ((float4*)s_g)[tid] = ((const float4*)gam)[tid];
            ((float4*)s_b)[tid] = ((const float4*)bet)[tid];
        }
        #pragma unroll
        for (int i = 0; i < 4; i++) {
            int idx = tid + i * 256;
            int row = idx >> 3, c4 = idx & 7;
            st[i] = g_stats[rowA + row];
            xrow[i] = A + (((size_t)(rowA + row)) << 9) + (c4 << 2);
        }
    }

    float acc[4][4][4];
    #pragma unroll
    for (int mt = 0; mt < 4; mt++)
        #pragma unroll
        for (int nt = 0; nt < 4; nt++)
            #pragma unroll
            for (int q = 0; q < 4; q++) acc[mt][nt][q] = 0.0f;

    // prologue: stage 0
    float4 vx[4];
    if (LNA) {
        #pragma unroll
        for (int i = 0; i < 4; i++) vx[i] = *(const float4*)(xrow[i]);
    } else {
        stage_cp(A, uA[0], rowA, 0, tid);
    }
    stage_cp(Bt, uB[0], rowB, 0, tid);
    CP_COMMIT();
    if (LNA) {
        __syncthreads();   // s_g/s_b ready
        #pragma unroll
        for (int i = 0; i < 4; i++) {
            int idx = tid + i * 256;
            int row = idx >> 3, c4 = idx & 7;
            float mu = st[i].x, inv = st[i].y;
            const float4 gm = *(const float4*)(s_g + (c4 << 2));
            const float4 bb = *(const float4*)(s_b + (c4 << 2));
            float4 o;
            o.x = to_tf32((vx[i].x - mu) * inv * gm.x + bb.x);
            o.y = to_tf32((vx[i].y - mu) * inv * gm.y + bb.y);
            o.z = to_tf32((vx[i].z - mu) * inv * gm.z + bb.z);
            o.w = to_tf32((vx[i].w - mu) * inv * gm.w + bb.w);
            *(float4*)(sA[0] + row * 128 + ((c4 ^ (row & 7)) << 4)) = o;
        }
    }
    CP_WAIT(0);
    __syncthreads();

    #pragma unroll 1
    for (int s = 0; s < 16; s++) {
        int b = s & 1;
        if (s + 1 < 16) {
            if (LNA) {
                #pragma unroll
                for (int i = 0; i < 4; i++)
                    vx[i] = *(const float4*)(xrow[i] + (s + 1) * 32);
            } else {
                stage_cp(A, uA[b ^ 1], rowA, (s + 1) * 32, tid);
            }
            stage_cp(Bt, uB[b ^ 1], rowB, (s + 1) * 32, tid);
            CP_COMMIT();
        }

        const char* cA = sA[b];
        const char* cB = sB[b];
        #pragma unroll
        for (int ks = 0; ks < 4; ks++) {
            uint32_t go0 = ((uint32_t)((2 * ks)     ^ g) << 4) + ((uint32_t)t4 << 2);
            uint32_t go1 = ((uint32_t)((2 * ks + 1) ^ g) << 4) + ((uint32_t)t4 << 2);
            float af[4][4];
            #pragma unroll
            for (int mt = 0; mt < 4; mt++) {
                const char* rp = cA + (wm * 64 + mt * 16 + g) * 128;
                af[mt][0] = *(const float*)(rp + go0);
                af[mt][1] = *(const float*)(rp + 8 * 128 + go0);
                af[mt][2] = *(const float*)(rp + go1);
                af[mt][3] = *(const float*)(rp + 8 * 128 + go1);
            }
            float bf[4][2];
            #pragma unroll
            for (int nt = 0; nt < 4; nt++) {
                const char* rp = cB + (wn * 32 + nt * 8 + g) * 128;
                bf[nt][0] = *(const float*)(rp + go0);
                bf[nt][1] = *(const float*)(rp + go1);
            }
            #pragma unroll
            for (int mt = 0; mt < 4; mt++)
                #pragma unroll
                for (int nt = 0; nt < 4; nt++)
                    mma_tf32(acc[mt][nt], af[mt][0], af[mt][1], af[mt][2], af[mt][3],
                             bf[nt][0], bf[nt][1]);
        }

        if (s + 1 < 16) {
            if (LNA) {
                int k0 = (s + 1) * 32;
                #pragma unroll
                for (int i = 0; i < 4; i++) {
                    int idx = tid + i * 256;
                    int row = idx >> 3, c4 = idx & 7;
                    float mu = st[i].x, inv = st[i].y;
                    const float4 gm = *(const float4*)(s_g + k0 + (c4 << 2));
                    const float4 bb = *(const float4*)(s_b + k0 + (c4 << 2));
                    float4 o;
                    o.x = to_tf32((vx[i].x - mu) * inv * gm.x + bb.x);
                    o.y = to_tf32((vx[i].y - mu) * inv * gm.y + bb.y);
                    o.z = to_tf32((vx[i].z - mu) * inv * gm.z + bb.z);
                    o.w = to_tf32((vx[i].w - mu) * inv * gm.w + bb.w);
                    *(float4*)(sA[b ^ 1] + row * 128 + ((c4 ^ (row & 7)) << 4)) = o;
                }
            }
            CP_WAIT(0);
        }
        __syncthreads();
    }

    // epilogue
    #pragma unroll
    for (int mt = 0; mt < 4; mt++) {
        size_t r0 = (size_t)rowA + wm * 64 + mt * 16 + g;
        size_t r1 = r0 + 8;
        #pragma unroll
        for (int nt = 0; nt < 4; nt++) {
            int col = bn * 128 + wn * 32 + nt * 8 + 2 * t4;
            float b0 = bias[col], b1 = bias[col + 1];
            float v0 = acc[mt][nt][0] + b0;
            float v1 = acc[mt][nt][1] + b1;
            float v2 = acc[mt][nt][2] + b0;
            float v3 = acc[mt][nt][3] + b1;
            if (EPI == 1) {
                const float* rr0 = resid + r0 * D_MODEL + col;
                const float* rr1 = resid + r1 * D_MODEL + col;
                v0 = rr0[0] + gelu_exact(v0);
                v1 = rr0[1] + gelu_exact(v1);
                v2 = rr1[0] + gelu_exact(v2);
                v3 = rr1[1] + gelu_exact(v3);
            }
            *(float2*)(C + r0 * D_MODEL + col) = make_float2(v0, v1);
            *(float2*)(C + r1 * D_MODEL + col) = make_float2(v2, v3);
        }
    }
}

// ---------------------------------------------------------------------------
// Bidirectional 32-tap FIR + D skip. R=8 consecutive outputs/thread,
// sliding register windows, f32x2 math, swizzled smem. Output tf32-rounded.
// ---------------------------------------------------------------------------
#define FT_BLK 1024
#define FIR_SLOTS (FT_BLK + 2 * NTAPS + 1)   // 1089
#define SU(i) su[(i) + ((i) >> 3)]

__global__ __launch_bounds__(128)
void fir_kernel(const float* __restrict__ Dvec)
{
    int c  = blockIdx.y;
    int b  = blockIdx.z;
    int t0 = blockIdx.x * FT_BLK;
    int tid = threadIdx.x;

    __shared__ float4 su[FIR_SLOTS + (FIR_SLOTS >> 3) + 1];
    __shared__ float  sk[NTAPS];

    const float4* u4 = (const float4*)g_z1;
    for (int i = tid; i < FIR_SLOTS; i += 128) {
        int t = t0 - 32 + i;
        float4 v = make_float4(0.f, 0.f, 0.f, 0.f);
        if (t >= 0 && t < L_SEQ) v = u4[((size_t)b * L_SEQ + t) * NC + c];
        SU(i) = v;
    }
    if (tid < NTAPS) sk[tid] = g_k[c * NTAPS + tid];
    __syncthreads();

    int w = tid * 8;
    float4 F[8], Bw[8];
    #pragma unroll
    for (int r = 0; r < 8; r++) { F[r] = SU(w + 32 + r); Bw[r] = SU(w + 33 + r); }

    float dv = Dvec[c];
    uint64_t dv2 = pk2(dv, dv);
    uint64_t aL[8], aH[8];
    #pragma unroll
    for (int r = 0; r < 8; r++) {
        aL[r] = mulx2(dv2, pk2(F[r].x, F[r].y));
        aH[r] = mulx2(dv2, pk2(F[r].z, F[r].w));
    }

    #pragma unroll
    for (int tau = 0; tau < NTAPS; tau++) {
        float kt = sk[tau];
        uint64_t k2 = pk2(kt, kt);
        #pragma unroll
        for (int r = 0; r < 8; r++) {
            uint64_t sL = addx2(pk2(F[r].x, F[r].y), pk2(Bw[r].x, Bw[r].y));
            uint64_t sH = addx2(pk2(F[r].z, F[r].w), pk2(Bw[r].z, Bw[r].w));
            aL[r] = fmax2(k2, sL, aL[r]);
            aH[r] = fmax2(k2, sH, aH[r]);
        }
        #pragma unroll
        for (int r = 7; r > 0; r--) F[r] = F[r - 1];
        F[0] = SU(w + 31 - tau);
        #pragma unroll
        for (int r = 0; r < 7; r++) Bw[r] = Bw[r + 1];
        Bw[7] = SU(w + 41 + tau);
    }

    float4* y4 = (float4*)g_y;
    #pragma unroll
    for (int r = 0; r < 8; r++) {
        float4 o;
        upk2(aL[r], o.x, o.y);
        upk2(aH[r], o.z, o.w);
        o.x = to_tf32(o.x); o.y = to_tf32(o.y); o.z = to_tf32(o.z); o.w = to_tf32(o.w);
        y4[((size_t)b * L_SEQ + t0 + w + r) * NC + c] = o;
    }
}

// ---------------------------------------------------------------------------
// Launch
// ---------------------------------------------------------------------------
extern "C" void kernel_launch(void* const* d_in, const int* in_sizes, int n_in,
                              void* d_out, int out_size)
{
    const float* x    = (const float*)d_in[0];
    const float* ln_g = (const float*)d_in[1];
    const float* ln_b = (const float*)d_in[2];
    const float* Win  = (const float*)d_in[3];
    const float* bin_ = (const float*)d_in[4];
    const float* Wout = (const float*)d_in[5];
    const float* bout = (const float*)d_in[6];
    const float* lre  = (const float*)d_in[7];
    const float* lim  = (const float*)d_in[8];
    const float* Bm   = (const float*)d_in[9];
    const float* cre  = (const float*)d_in[10];
    const float* cim  = (const float*)d_in[11];
    const float* Dvec = (const float*)d_in[12];
    float* out = (float*)d_out;

    float *z1, *y, *wti, *wto;
    cudaGetSymbolAddress((void**)&z1,  g_z1);
    cudaGetSymbolAddress((void**)&y,   g_y);
    cudaGetSymbolAddress((void**)&wti, g_wti);
    cudaGetSymbolAddress((void**)&wto, g_wto);

    cudaFuncSetAttribute(gemm_mma<0,1>, cudaFuncAttributeMaxDynamicSharedMemorySize, GEMM_SMEM);
    cudaFuncSetAttribute(gemm_mma<1,0>, cudaFuncAttributeMaxDynamicSharedMemorySize, GEMM_SMEM);

    // 1. combined prep: LN stats + Win^T + Wout^T + FIR taps
    prep_kernel<<<PREP_KGEN, 256>>>(x, Win, Wout, lre, lim, Bm, cre, cim);

    // 2. in-projection with fused LayerNorm A-producer
    gemm_mma<0,1><<<dim3(4, 256), 256, GEMM_SMEM>>>(x, wti, bin_, nullptr, z1, ln_g, ln_b);

    // 3. bidirectional FIR + D skip
    fir_kernel<<<dim3(L_SEQ / FT_BLK, NC, B_SZ), 128>>>(Dvec);

    // 4. out-projection + gelu + residual -> d_out
    gemm_mma<1,0><<<dim3(4, 256), 256, GEMM_SMEM>>>(y, wto, bout, x, out, nullptr, nullptr);
}

// round 8
// speedup vs baseline: 1.2037x; 1.2037x over previous
#include <cuda_runtime.h>
#include <cuda_bf16.h>
#include <math.h>
#include <stdint.h>

// Problem constants
#define B_SZ   8
#define L_SEQ  4096
#define D_MODEL 512
#define NC     128
#define NSTATE 64
#define NTAPS  32
#define M_ROWS (B_SZ * L_SEQ)   // 32768

// Scratch
__device__ float g_z  [M_ROWS * D_MODEL];   // LN output (tf32-rounded)
__device__ float g_z1 [M_ROWS * D_MODEL];   // in-proj output
__device__ float g_y  [M_ROWS * D_MODEL];   // FIR output (tf32-rounded)
__device__ float g_k  [NC * NTAPS];
__device__ float g_wti[D_MODEL * D_MODEL];  // Win^T, tf32-rounded
__device__ float g_wto[D_MODEL * D_MODEL];  // Wout^T, tf32-rounded

// ---------------------------------------------------------------------------
// Helpers
// ---------------------------------------------------------------------------
__device__ __forceinline__ float to_tf32(float f) {
    uint32_t u;
    asm("cvt.rna.tf32.f32 %0, %1;" : "=r"(u) : "f"(f));
    return __uint_as_float(u);
}
__device__ __forceinline__ uint32_t smem_u32(const void* p) {
    uint32_t a;
    asm("{ .reg .u64 t; cvta.to.shared.u64 t, %1; cvt.u32.u64 %0, t; }" : "=r"(a) : "l"(p));
    return a;
}
__device__ __forceinline__ void cp16(uint32_t dst, const void* src) {
    asm volatile("cp.async.cg.shared.global [%0], [%1], 16;" :: "r"(dst), "l"(src));
}
#define CP_COMMIT() asm volatile("cp.async.commit_group;" ::: "memory")
#define CP_WAIT(n)  asm volatile("cp.async.wait_group %0;" :: "n"(n) : "memory")

// m16n8k8 tf32 warp MMA
__device__ __forceinline__ void mma_tf32(float c[4],
                                         float a0, float a1, float a2, float a3,
                                         float b0, float b1)
{
    asm volatile(
        "mma.sync.aligned.m16n8k8.row.col.f32.tf32.tf32.f32 "
        "{%0,%1,%2,%3}, {%4,%5,%6,%7}, {%8,%9}, {%0,%1,%2,%3};"
        : "+f"(c[0]), "+f"(c[1]), "+f"(c[2]), "+f"(c[3])
        : "r"(__float_as_uint(a0)), "r"(__float_as_uint(a1)),
          "r"(__float_as_uint(a2)), "r"(__float_as_uint(a3)),
          "r"(__float_as_uint(b0)), "r"(__float_as_uint(b1)));
}

// f32x2 packed math
__device__ __forceinline__ uint64_t pk2(float a, float b) {
    uint64_t r; asm("mov.b64 %0, {%1, %2};" : "=l"(r) : "f"(a), "f"(b)); return r;
}
__device__ __forceinline__ void upk2(uint64_t v, float& a, float& b) {
    asm("mov.b64 {%0, %1}, %2;" : "=f"(a), "=f"(b) : "l"(v));
}
__device__ __forceinline__ uint64_t addx2(uint64_t a, uint64_t b) {
    uint64_t r; asm("add.rn.f32x2 %0, %1, %2;" : "=l"(r) : "l"(a), "l"(b)); return r;
}
__device__ __forceinline__ uint64_t mulx2(uint64_t a, uint64_t b) {
    uint64_t r; asm("mul.rn.f32x2 %0, %1, %2;" : "=l"(r) : "l"(a), "l"(b)); return r;
}
__device__ __forceinline__ uint64_t fmax2(uint64_t a, uint64_t b, uint64_t c) {
    uint64_t r; asm("fma.rn.f32x2 %0, %1, %2, %3;" : "=l"(r) : "l"(a), "l"(b), "l"(c)); return r;
}

// ---------------------------------------------------------------------------
// Combined prep kernel:
//   [0, 16384)        LayerNorm, 2 rows per block (writes g_z, tf32-rounded)
//   [16384, 16896)    Win^T / Wout^T transpose + tf32 round (32x32 tiles)
//   [16896, 16912)    FIR taps (8 chunks per block)
// ---------------------------------------------------------------------------
#define PREP_LN    16384
#define PREP_WT    (PREP_LN + 512)
#define PREP_TOTAL (PREP_WT + 16)

__global__ __launch_bounds__(256)
void prep_kernel(const float* __restrict__ x,
                 const float* __restrict__ gam, const float* __restrict__ bet,
                 const float* __restrict__ Win, const float* __restrict__ Wout,
                 const float* __restrict__ lre, const float* __restrict__ lim,
                 const float* __restrict__ Bm,  const float* __restrict__ cre,
                 const float* __restrict__ cim)
{
    int bid = blockIdx.x;
    int tid = threadIdx.x;

    if (bid < PREP_LN) {
        // LayerNorm: 2 rows per block, 128 threads per row
        int half = tid >> 7;
        int t    = tid & 127;
        int row  = bid * 2 + half;
        float4 v = ((const float4*)(x + (size_t)row * D_MODEL))[t];
        float s  = v.x + v.y + v.z + v.w;
        float sq = v.x*v.x + v.y*v.y + v.z*v.z + v.w*v.w;
        #pragma unroll
        for (int off = 16; off > 0; off >>= 1) {
            s  += __shfl_xor_sync(0xFFFFFFFFu, s,  off);
            sq += __shfl_xor_sync(0xFFFFFFFFu, sq, off);
        }
        __shared__ float ss[8], ssq[8];
        int warp = tid >> 5, lane = tid & 31;
        if (lane == 0) { ss[warp] = s; ssq[warp] = sq; }
        __syncthreads();
        int w0 = half * 4;
        float tots = ss[w0] + ss[w0+1] + ss[w0+2] + ss[w0+3];
        float totq = ssq[w0] + ssq[w0+1] + ssq[w0+2] + ssq[w0+3];
        float mu  = tots * (1.0f / D_MODEL);
        float var = totq * (1.0f / D_MODEL) - mu * mu;
        float inv = rsqrtf(var + 1e-5f);
        float4 gg = ((const float4*)gam)[t];
        float4 bb = ((const float4*)bet)[t];
        float4 o;
        o.x = to_tf32((v.x - mu) * inv * gg.x + bb.x);
        o.y = to_tf32((v.y - mu) * inv * gg.y + bb.y);
        o.z = to_tf32((v.z - mu) * inv * gg.z + bb.z);
        o.w = to_tf32((v.w - mu) * inv * gg.w + bb.w);
        ((float4*)(g_z + (size_t)row * D_MODEL))[t] = o;
    } else if (bid < PREP_WT) {
        // transpose + tf32 round, 32x32 tile
        int ti = bid - PREP_LN;
        const float* W;
        float* Wt;
        if (ti < 256) { W = Win;  Wt = g_wti; }
        else          { W = Wout; Wt = g_wto; ti -= 256; }
        int n0 = (ti & 15) * 32, k0 = (ti >> 4) * 32;
        __shared__ float tile[32][33];
        int tx = tid & 31, ty = tid >> 5;   // 32 x 8
        #pragma unroll
        for (int j = 0; j < 32; j += 8)
            tile[ty + j][tx] = W[(size_t)(k0 + ty + j) * D_MODEL + n0 + tx];
        __syncthreads();
        #pragma unroll
        for (int j = 0; j < 32; j += 8)
            Wt[(size_t)(n0 + ty + j) * D_MODEL + k0 + tx] = to_tf32(tile[tx][ty + j]);
    } else {
        // FIR taps
        int c = (bid - PREP_WT) * 8 + (tid >> 5);
        int tau = tid & 31;
        float ft = (float)tau;
        float acc = 0.0f;
        #pragma unroll 8
        for (int n = 0; n < NSTATE; n++) {
            int idx = c * NSTATE + n;
            float re = lre[idx], im = lim[idx], bn = Bm[idx];
            float cr = cre[idx] * bn, ci = cim[idx] * bn;
            float s, co;
            sincosf(im * ft, &s, &co);
            acc += expf(re * ft) * (cr * co - ci * s);
        }
        g_k[c * NTAPS + tau] = acc;
    }
}

// ---------------------------------------------------------------------------
// Warp-MMA tf32 GEMM. CTA tile 128x128, BK=32, 8 warps (2m x 4n), m16n8k8.
// 3-stage cp.async pipeline, one __syncthreads per stage, XOR-swizzled smem.
// ---------------------------------------------------------------------------
__device__ __forceinline__ float gelu_exact(float v) {
    return 0.5f * v * (1.0f + erff(v * 0.70710678118654752f));
}

#define STG_A 16384                      // 128 rows x 128B
#define STG_B 16384
#define STG_BYTES (STG_A + STG_B)        // 32KB per stage
#define NSTAGE 3
#define GEMM_SMEM (NSTAGE * STG_BYTES)   // 96KB

__device__ __forceinline__ void stage_cp(const float* __restrict__ Asrc,
                                         const float* __restrict__ Bsrc,
                                         uint32_t sbuf, int rowA, int rowB,
                                         int k0, int tid)
{
    #pragma unroll
    for (int i = 0; i < 4; i++) {
        int idx = tid + i * 256;
        int row = idx >> 3, c4 = idx & 7;
        uint32_t so = row * 128 + ((c4 ^ (row & 7)) << 4);
        cp16(sbuf + so,
             Asrc + (((size_t)(rowA + row)) << 9) + k0 + (c4 << 2));
        cp16(sbuf + STG_A + so,
             Bsrc + (((size_t)(rowB + row)) << 9) + k0 + (c4 << 2));
    }
}

template<int EPI>
__global__ __launch_bounds__(256, 2)
void gemm_mma(const float* __restrict__ A, const float* __restrict__ Bt,
              const float* __restrict__ bias, const float* __restrict__ resid,
              float* __restrict__ C)
{
    extern __shared__ __align__(16) char sm[];
    uint32_t ubase = smem_u32(sm);

    int tid = threadIdx.x;
    int lane = tid & 31;
    int wid  = tid >> 5;
    int wm = wid >> 2;       // 0..1
    int wn = wid & 3;        // 0..3
    int g  = lane >> 2;      // 0..7
    int t4 = lane & 3;       // 0..3

    int bn = blockIdx.x, bm = blockIdx.y;
    int rowA = bm * 128, rowB = bn * 128;

    float acc[4][4][4];
    #pragma unroll
    for (int mt = 0; mt < 4; mt++)
        #pragma unroll
        for (int nt = 0; nt < 4; nt++)
            #pragma unroll
            for (int q = 0; q < 4; q++) acc[mt][nt][q] = 0.0f;

    // prologue: stages 0, 1 in flight
    stage_cp(A, Bt, ubase,             rowA, rowB,  0, tid);
    CP_COMMIT();
    stage_cp(A, Bt, ubase + STG_BYTES, rowA, rowB, 32, tid);
    CP_COMMIT();

    #pragma unroll 1
    for (int s = 0; s < 16; s++) {
        uint32_t ub = ubase + (uint32_t)(s % NSTAGE) * STG_BYTES;
        if (s + 2 < 16) { CP_WAIT(1); } else { CP_WAIT(0); }
        __syncthreads();
        if (s + 2 < 16) {
            stage_cp(A, Bt, ubase + (uint32_t)((s + 2) % NSTAGE) * STG_BYTES,
                     rowA, rowB, (s + 2) * 32, tid);
            CP_COMMIT();
        }

        const char* cA = sm + (s % NSTAGE) * STG_BYTES;
        const char* cB = cA + STG_A;
        #pragma unroll
        for (int ks = 0; ks < 4; ks++) {
            uint32_t go0 = ((uint32_t)((2 * ks)     ^ g) << 4) + ((uint32_t)t4 << 2);
            uint32_t go1 = ((uint32_t)((2 * ks + 1) ^ g) << 4) + ((uint32_t)t4 << 2);
            float af[4][4];
            #pragma unroll
            for (int mt = 0; mt < 4; mt++) {
                const char* rp = cA + (wm * 64 + mt * 16 + g) * 128;
                af[mt][0] = *(const float*)(rp + go0);
                af[mt][1] = *(const float*)(rp + 8 * 128 + go0);
                af[mt][2] = *(const float*)(rp + go1);
                af[mt][3] = *(const float*)(rp + 8 * 128 + go1);
            }
            float bf[4][2];
            #pragma unroll
            for (int nt = 0; nt < 4; nt++) {
                const char* rp = cB + (wn * 32 + nt * 8 + g) * 128;
                bf[nt][0] = *(const float*)(rp + go0);
                bf[nt][1] = *(const float*)(rp + go1);
            }
            #pragma unroll
            for (int mt = 0; mt < 4; mt++)
                #pragma unroll
                for (int nt = 0; nt < 4; nt++)
                    mma_tf32(acc[mt][nt], af[mt][0], af[mt][1], af[mt][2], af[mt][3],
                             bf[nt][0], bf[nt][1]);
        }
        __syncthreads();
    }

    // epilogue
    #pragma unroll
    for (int mt = 0; mt < 4; mt++) {
        size_t r0 = (size_t)rowA + wm * 64 + mt * 16 + g;
        size_t r1 = r0 + 8;
        #pragma unroll
        for (int nt = 0; nt < 4; nt++) {
            int col = bn * 128 + wn * 32 + nt * 8 + 2 * t4;
            float b0 = bias[col], b1 = bias[col + 1];
            float v0 = acc[mt][nt][0] + b0;
            float v1 = acc[mt][nt][1] + b1;
            float v2 = acc[mt][nt][2] + b0;
            float v3 = acc[mt][nt][3] + b1;
            if (EPI == 1) {
                const float* rr0 = resid + r0 * D_MODEL + col;
                const float* rr1 = resid + r1 * D_MODEL + col;
                v0 = rr0[0] + gelu_exact(v0);
                v1 = rr0[1] + gelu_exact(v1);
                v2 = rr1[0] + gelu_exact(v2);
                v3 = rr1[1] + gelu_exact(v3);
            }
            *(float2*)(C + r0 * D_MODEL + col) = make_float2(v0, v1);
            *(float2*)(C + r1 * D_MODEL + col) = make_float2(v2, v3);
        }
    }
}

// ---------------------------------------------------------------------------
// Bidirectional 32-tap FIR + D skip. R=8 consecutive outputs/thread,
// sliding register windows, f32x2 math, swizzled smem. Output tf32-rounded.
// ---------------------------------------------------------------------------
#define FT_BLK 1024
#define FIR_SLOTS (FT_BLK + 2 * NTAPS + 1)   // 1089
#define SU(i) su[(i) + ((i) >> 3)]

__global__ __launch_bounds__(128)
void fir_kernel(const float* __restrict__ Dvec)
{
    int c  = blockIdx.y;
    int b  = blockIdx.z;
    int t0 = blockIdx.x * FT_BLK;
    int tid = threadIdx.x;

    __shared__ float4 su[FIR_SLOTS + (FIR_SLOTS >> 3) + 1];
    __shared__ float  sk[NTAPS];

    const float4* u4 = (const float4*)g_z1;
    for (int i = tid; i < FIR_SLOTS; i += 128) {
        int t = t0 - 32 + i;
        float4 v = make_float4(0.f, 0.f, 0.f, 0.f);
        if (t >= 0 && t < L_SEQ) v = u4[((size_t)b * L_SEQ + t) * NC + c];
        SU(i) = v;
    }
    if (tid < NTAPS) sk[tid] = g_k[c * NTAPS + tid];
    __syncthreads();

    int w = tid * 8;
    float4 F[8], Bw[8];
    #pragma unroll
    for (int r = 0; r < 8; r++) { F[r] = SU(w + 32 + r); Bw[r] = SU(w + 33 + r); }

    float dv = Dvec[c];
    uint64_t dv2 = pk2(dv, dv);
    uint64_t aL[8], aH[8];
    #pragma unroll
    for (int r = 0; r < 8; r++) {
        aL[r] = mulx2(dv2, pk2(F[r].x, F[r].y));
        aH[r] = mulx2(dv2, pk2(F[r].z, F[r].w));
    }

    #pragma unroll
    for (int tau = 0; tau < NTAPS; tau++) {
        float kt = sk[tau];
        uint64_t k2 = pk2(kt, kt);
        #pragma unroll
        for (int r = 0; r < 8; r++) {
            uint64_t sL = addx2(pk2(F[r].x, F[r].y), pk2(Bw[r].x, Bw[r].y));
            uint64_t sH = addx2(pk2(F[r].z, F[r].w), pk2(Bw[r].z, Bw[r].w));
            aL[r] = fmax2(k2, sL, aL[r]);
            aH[r] = fmax2(k2, sH, aH[r]);
        }
        #pragma unroll
        for (int r = 7; r > 0; r--) F[r] = F[r - 1];
        F[0] = SU(w + 31 - tau);
        #pragma unroll
        for (int r = 0; r < 7; r++) Bw[r] = Bw[r + 1];
        Bw[7] = SU(w + 41 + tau);
    }

    float4* y4 = (float4*)g_y;
    #pragma unroll
    for (int r = 0; r < 8; r++) {
        float4 o;
        upk2(aL[r], o.x, o.y);
        upk2(aH[r], o.z, o.w);
        o.x = to_tf32(o.x); o.y = to_tf32(o.y); o.z = to_tf32(o.z); o.w = to_tf32(o.w);
        y4[((size_t)b * L_SEQ + t0 + w + r) * NC + c] = o;
    }
}

// ---------------------------------------------------------------------------
// Launch
// ---------------------------------------------------------------------------
extern "C" void kernel_launch(void* const* d_in, const int* in_sizes, int n_in,
                              void* d_out, int out_size)
{
    const float* x    = (const float*)d_in[0];
    const float* ln_g = (const float*)d_in[1];
    const float* ln_b = (const float*)d_in[2];
    const float* Win  = (const float*)d_in[3];
    const float* bin_ = (const float*)d_in[4];
    const float* Wout = (const float*)d_in[5];
    const float* bout = (const float*)d_in[6];
    const float* lre  = (const float*)d_in[7];
    const float* lim  = (const float*)d_in[8];
    const float* Bm   = (const float*)d_in[9];
    const float* cre  = (const float*)d_in[10];
    const float* cim  = (const float*)d_in[11];
    const float* Dvec = (const float*)d_in[12];
    float* out = (float*)d_out;

    float *z, *z1, *y, *wti, *wto;
    cudaGetSymbolAddress((void**)&z,   g_z);
    cudaGetSymbolAddress((void**)&z1,  g_z1);
    cudaGetSymbolAddress((void**)&y,   g_y);
    cudaGetSymbolAddress((void**)&wti, g_wti);
    cudaGetSymbolAddress((void**)&wto, g_wto);

    cudaFuncSetAttribute(gemm_mma<0>, cudaFuncAttributeMaxDynamicSharedMemorySize, GEMM_SMEM);
    cudaFuncSetAttribute(gemm_mma<1>, cudaFuncAttributeMaxDynamicSharedMemorySize, GEMM_SMEM);

    // 1. combined prep: LayerNorm + Win^T + Wout^T + FIR taps
    prep_kernel<<<PREP_TOTAL, 256>>>(x, ln_g, ln_b, Win, Wout, lre, lim, Bm, cre, cim);

    // 2. in-projection: z1 = z @ Win + bin
    gemm_mma<0><<<dim3(4, 256), 256, GEMM_SMEM>>>(z, wti, bin_, nullptr, z1);

    // 3. bidirectional FIR + D skip
    fir_kernel<<<dim3(L_SEQ / FT_BLK, NC, B_SZ), 128>>>(Dvec);

    // 4. out-projection + gelu + residual -> d_out
    gemm_mma<1><<<dim3(4, 256), 256, GEMM_SMEM>>>(y, wto, bout, x, out);
}